// round 2
// baseline (speedup 1.0000x reference)
#include <cuda_runtime.h>
#include <math.h>

#define H   256
#define G4  1024
#define BSZ 2048
#define OSZ 128
#define TSTEPS 100
#define BT  16
#define NCTA (BSZ/BT)     // 128
#define NTHR 256
#define HS  20            // padded row stride for h_s (conflict-free transposed writes)

// Scratch in device globals (no allocations allowed in kernel_launch)
__device__ float g_WhhT[H*G4];
__device__ float g_WihT[H*G4];
__device__ float g_WoutT[H*OSZ];
__device__ float g_xg[BSZ*G4];

__device__ __forceinline__ float sigmoidf_(float x) {
    return 1.0f / (1.0f + __expf(-x));
}

// ---------------------------------------------------------------------------
// One-time: transpose weights to k-major layouts
// ---------------------------------------------------------------------------
__global__ void transpose_kernel(const float* __restrict__ Wih,
                                 const float* __restrict__ Whh,
                                 const float* __restrict__ Wout) {
    int idx = blockIdx.x * blockDim.x + threadIdx.x;
    if (idx < H * G4) {
        int k = idx >> 10;          // 0..255
        int g = idx & (G4 - 1);     // 0..1023
        g_WihT[idx] = Wih[g * H + k];
        g_WhhT[idx] = Whh[g * H + k];
    }
    if (idx < H * OSZ) {
        int k = idx >> 7;           // 0..255
        int o = idx & (OSZ - 1);    // 0..127
        g_WoutT[idx] = Wout[o * H + k];
    }
}

// ---------------------------------------------------------------------------
// One-time: x_gates = C @ W_ih^T + b_ih + b_hh   (constant across all steps)
// ---------------------------------------------------------------------------
__global__ void __launch_bounds__(NTHR) xgates_kernel(const float* __restrict__ C,
                                                      const float* __restrict__ b_ih,
                                                      const float* __restrict__ b_hh) {
    __shared__ __align__(16) float c_s[H * HS];
    int tid = threadIdx.x;
    int row0 = blockIdx.x * BT;

    // load C tile transposed into [k][b] layout
    for (int i = tid; i < BT * H; i += NTHR) {
        int b = i >> 8;
        int k = i & (H - 1);
        c_s[k * HS + b] = C[(size_t)(row0 + b) * H + k];
    }
    __syncthreads();

    int bb = tid & 3;       // b-group: rows 4*bb .. 4*bb+3
    int jj = tid >> 2;      // 0..63, covers j = jj*4 .. jj*4+3 within each gate

    float acc[4][16];
    #pragma unroll
    for (int gate = 0; gate < 4; gate++) {
        int g0 = gate * H + jj * 4;
        float4 bi = *(const float4*)(b_ih + g0);
        float4 bh = *(const float4*)(b_hh + g0);
        float s0 = bi.x + bh.x, s1 = bi.y + bh.y, s2 = bi.z + bh.z, s3 = bi.w + bh.w;
        #pragma unroll
        for (int b = 0; b < 4; b++) {
            acc[b][gate*4+0] = s0; acc[b][gate*4+1] = s1;
            acc[b][gate*4+2] = s2; acc[b][gate*4+3] = s3;
        }
    }

    #pragma unroll 4
    for (int k = 0; k < H; k++) {
        float4 hv = *(const float4*)(c_s + k * HS + 4 * bb);
        float hb[4] = {hv.x, hv.y, hv.z, hv.w};
        #pragma unroll
        for (int gate = 0; gate < 4; gate++) {
            float4 wv = *(const float4*)(g_WihT + (size_t)k * G4 + gate * H + jj * 4);
            #pragma unroll
            for (int b = 0; b < 4; b++) {
                acc[b][gate*4+0] += hb[b] * wv.x;
                acc[b][gate*4+1] += hb[b] * wv.y;
                acc[b][gate*4+2] += hb[b] * wv.z;
                acc[b][gate*4+3] += hb[b] * wv.w;
            }
        }
    }

    #pragma unroll
    for (int b = 0; b < 4; b++) {
        #pragma unroll
        for (int gate = 0; gate < 4; gate++) {
            float4 v = make_float4(acc[b][gate*4+0], acc[b][gate*4+1],
                                   acc[b][gate*4+2], acc[b][gate*4+3]);
            *(float4*)(g_xg + (size_t)(row0 + 4*bb + b) * G4 + gate * H + jj * 4) = v;
        }
    }
}

// ---------------------------------------------------------------------------
// Main persistent LSTM kernel: each CTA owns BT=16 batch rows, loops T steps.
// No inter-CTA dependency (recurrence is independent per batch row).
// ---------------------------------------------------------------------------
__global__ void __launch_bounds__(NTHR, 1) lstm_kernel(const float* __restrict__ b_out,
                                                       float* __restrict__ ys) {
    __shared__ __align__(16) float h_s[H * HS];
    int tid = threadIdx.x;
    int row0 = blockIdx.x * BT;

    int bb = tid & 3;
    int jj = tid >> 2;

    // y-GEMM mapping: each thread: 2 b-rows x 4 o-cols
    int ob = tid & 31;      // o-group: cols 4*ob .. 4*ob+3
    int br = tid >> 5;      // b-pair: rows 2*br, 2*br+1

    for (int i = tid; i < H * HS; i += NTHR) h_s[i] = 0.0f;

    float cst[4][4];
    #pragma unroll
    for (int b = 0; b < 4; b++)
        #pragma unroll
        for (int d = 0; d < 4; d++) cst[b][d] = 0.0f;

    float4 bo = *(const float4*)(b_out + ob * 4);

    const float* xgp = g_xg + (size_t)row0 * G4;
    __syncthreads();

    for (int t = 0; t < TSTEPS; t++) {
        // ---- gates = x_gates + h @ W_hh^T (register-tiled, 64 accums/thread) ----
        float acc[4][16];
        #pragma unroll
        for (int b = 0; b < 4; b++) {
            #pragma unroll
            for (int gate = 0; gate < 4; gate++) {
                float4 v = *(const float4*)(xgp + (size_t)(4*bb + b) * G4 + gate * H + jj * 4);
                acc[b][gate*4+0] = v.x; acc[b][gate*4+1] = v.y;
                acc[b][gate*4+2] = v.z; acc[b][gate*4+3] = v.w;
            }
        }

        #pragma unroll 4
        for (int k = 0; k < H; k++) {
            float4 hv = *(const float4*)(h_s + k * HS + 4 * bb);
            float hb[4] = {hv.x, hv.y, hv.z, hv.w};
            #pragma unroll
            for (int gate = 0; gate < 4; gate++) {
                float4 wv = *(const float4*)(g_WhhT + (size_t)k * G4 + gate * H + jj * 4);
                #pragma unroll
                for (int b = 0; b < 4; b++) {
                    acc[b][gate*4+0] += hb[b] * wv.x;
                    acc[b][gate*4+1] += hb[b] * wv.y;
                    acc[b][gate*4+2] += hb[b] * wv.z;
                    acc[b][gate*4+3] += hb[b] * wv.w;
                }
            }
        }
        __syncthreads();   // all reads of old h_s done before writes

        // ---- cell update (fully register-local: thread owns matching i,f,g,o) ----
        #pragma unroll
        for (int b = 0; b < 4; b++) {
            #pragma unroll
            for (int d = 0; d < 4; d++) {
                float iv = acc[b][0  + d];
                float fv = acc[b][4  + d];
                float gv = acc[b][8  + d];
                float ov = acc[b][12 + d];
                float c = sigmoidf_(fv) * cst[b][d] + sigmoidf_(iv) * tanhf(gv);
                cst[b][d] = c;
                float h = sigmoidf_(ov) * tanhf(c);
                h_s[(jj * 4 + d) * HS + 4 * bb + b] = h;   // transposed [k][b] write
            }
        }
        __syncthreads();   // h_new visible to all

        // ---- y = h_new @ W_out^T + b_out ----
        float ya[2][4] = {{bo.x, bo.y, bo.z, bo.w}, {bo.x, bo.y, bo.z, bo.w}};
        #pragma unroll 8
        for (int k = 0; k < H; k++) {
            float2 hp = *(const float2*)(h_s + k * HS + 2 * br);
            float4 wv = *(const float4*)(g_WoutT + (size_t)k * OSZ + ob * 4);
            ya[0][0] += hp.x * wv.x; ya[0][1] += hp.x * wv.y;
            ya[0][2] += hp.x * wv.z; ya[0][3] += hp.x * wv.w;
            ya[1][0] += hp.y * wv.x; ya[1][1] += hp.y * wv.y;
            ya[1][2] += hp.y * wv.z; ya[1][3] += hp.y * wv.w;
        }
        float* yp = ys + ((size_t)t * BSZ + row0) * OSZ;
        *(float4*)(yp + (size_t)(2*br)     * OSZ + ob * 4) =
            make_float4(ya[0][0], ya[0][1], ya[0][2], ya[0][3]);
        *(float4*)(yp + (size_t)(2*br + 1) * OSZ + ob * 4) =
            make_float4(ya[1][0], ya[1][1], ya[1][2], ya[1][3]);
        // no barrier needed: next k-loop only READS h_s; next write is after next sync
    }
}

// ---------------------------------------------------------------------------
extern "C" void kernel_launch(void* const* d_in, const int* in_sizes, int n_in,
                              void* d_out, int out_size) {
    const float* C    = (const float*)d_in[0];
    const float* Wih  = (const float*)d_in[1];
    const float* Whh  = (const float*)d_in[2];
    const float* bih  = (const float*)d_in[3];
    const float* bhh  = (const float*)d_in[4];
    const float* Wout = (const float*)d_in[5];
    const float* bout = (const float*)d_in[6];
    float* ys = (float*)d_out;

    transpose_kernel<<<(H * G4 + 255) / 256, 256>>>(Wih, Whh, Wout);
    xgates_kernel<<<NCTA, NTHR>>>(C, bih, bhh);
    lstm_kernel<<<NCTA, NTHR>>>(bout, ys);
}

// round 9
// speedup vs baseline: 1.2745x; 1.2745x over previous
#include <cuda_runtime.h>
#include <math.h>

#define H   256
#define G4  1024
#define BSZ 2048
#define OSZ 128
#define TSTEPS 100
#define BT  16
#define NCTA (BSZ/BT)     // 128
#define NTHR 256
#define HS  20            // padded row stride for h_s (conflict-free transposed writes)

typedef unsigned long long ull;

// Scratch in device globals (no allocations allowed in kernel_launch)
__device__ float g_WhhT[H*G4];
__device__ float g_WihT[H*G4];
__device__ float g_WoutT[H*OSZ];
__device__ float g_xg[BSZ*G4];

// ---------------------------------------------------------------------------
// f32x2 packed-FMA helpers (sm_100+ : SASS FFMA2, one issue = two fp32 FMAs)
// ---------------------------------------------------------------------------
__device__ __forceinline__ void fma2(ull &acc, ull a, ull b) {
    asm("fma.rn.f32x2 %0, %1, %2, %0;" : "+l"(acc) : "l"(a), "l"(b));
}
__device__ __forceinline__ ull pack2(float lo, float hi) {
    ull r; asm("mov.b64 %0, {%1, %2};" : "=l"(r) : "f"(lo), "f"(hi)); return r;
}
__device__ __forceinline__ void unpack2(ull v, float &lo, float &hi) {
    asm("mov.b64 {%0, %1}, %2;" : "=f"(lo), "=f"(hi) : "l"(v));
}

// Fast activations: EX2 + RCP.approx (rel err ~1e-6, vs 1e-3 tolerance)
__device__ __forceinline__ float fast_sigmoid(float x) {
    float e = __expf(-x);                 // FMA-scale + MUFU.EX2
    float r; asm("rcp.approx.f32 %0, %1;" : "=f"(r) : "f"(1.0f + e));
    return r;
}
__device__ __forceinline__ float fast_tanh(float x) {
    // tanh(x) = 2*sigmoid(2x) - 1
    float e = __expf(-2.0f * x);
    float r; asm("rcp.approx.f32 %0, %1;" : "=f"(r) : "f"(1.0f + e));
    return __fmaf_rn(2.0f, r, -1.0f);
}

// ---------------------------------------------------------------------------
// One-time: transpose weights to k-major layouts
// ---------------------------------------------------------------------------
__global__ void transpose_kernel(const float* __restrict__ Wih,
                                 const float* __restrict__ Whh,
                                 const float* __restrict__ Wout) {
    int idx = blockIdx.x * blockDim.x + threadIdx.x;
    if (idx < H * G4) {
        int k = idx >> 10;
        int g = idx & (G4 - 1);
        g_WihT[idx] = Wih[g * H + k];
        g_WhhT[idx] = Whh[g * H + k];
    }
    if (idx < H * OSZ) {
        int k = idx >> 7;
        int o = idx & (OSZ - 1);
        g_WoutT[idx] = Wout[o * H + k];
    }
}

// ---------------------------------------------------------------------------
// One-time: x_gates = C @ W_ih^T + b_ih + b_hh
// ---------------------------------------------------------------------------
__global__ void __launch_bounds__(NTHR) xgates_kernel(const float* __restrict__ C,
                                                      const float* __restrict__ b_ih,
                                                      const float* __restrict__ b_hh) {
    __shared__ __align__(16) float c_s[H * HS];
    int tid = threadIdx.x;
    int row0 = blockIdx.x * BT;

    for (int i = tid; i < BT * H; i += NTHR) {
        int b = i >> 8;
        int k = i & (H - 1);
        c_s[k * HS + b] = C[(size_t)(row0 + b) * H + k];
    }
    __syncthreads();

    int bb = tid & 3;
    int jj = tid >> 2;

    ull acc2[4][8];
    #pragma unroll
    for (int gate = 0; gate < 4; gate++) {
        int g0 = gate * H + jj * 4;
        float4 bi = *(const float4*)(b_ih + g0);
        float4 bh = *(const float4*)(b_hh + g0);
        ull s01 = pack2(bi.x + bh.x, bi.y + bh.y);
        ull s23 = pack2(bi.z + bh.z, bi.w + bh.w);
        #pragma unroll
        for (int b = 0; b < 4; b++) {
            acc2[b][gate*2+0] = s01;
            acc2[b][gate*2+1] = s23;
        }
    }

    #pragma unroll 4
    for (int k = 0; k < H; k++) {
        float4 hv = *(const float4*)(c_s + k * HS + 4 * bb);
        ull h2[4] = { pack2(hv.x, hv.x), pack2(hv.y, hv.y),
                      pack2(hv.z, hv.z), pack2(hv.w, hv.w) };
        #pragma unroll
        for (int gate = 0; gate < 4; gate++) {
            ulonglong2 wv = *(const ulonglong2*)(g_WihT + (size_t)k * G4 + gate * H + jj * 4);
            #pragma unroll
            for (int b = 0; b < 4; b++) {
                fma2(acc2[b][gate*2+0], h2[b], wv.x);
                fma2(acc2[b][gate*2+1], h2[b], wv.y);
            }
        }
    }

    #pragma unroll
    for (int b = 0; b < 4; b++) {
        #pragma unroll
        for (int gate = 0; gate < 4; gate++) {
            ulonglong2 v;
            v.x = acc2[b][gate*2+0];
            v.y = acc2[b][gate*2+1];
            *(ulonglong2*)(g_xg + (size_t)(row0 + 4*bb + b) * G4 + gate * H + jj * 4) = v;
        }
    }
}

// ---------------------------------------------------------------------------
// Main persistent LSTM kernel: each CTA owns BT=16 batch rows, loops T steps.
// ---------------------------------------------------------------------------
__global__ void __launch_bounds__(NTHR, 1) lstm_kernel(const float* __restrict__ b_out,
                                                       float* __restrict__ ys) {
    __shared__ __align__(16) float h_s[H * HS];
    int tid = threadIdx.x;
    int row0 = blockIdx.x * BT;

    int bb = tid & 3;
    int jj = tid >> 2;

    // y-GEMM mapping: each thread: 2 b-rows x 4 o-cols
    int ob = tid & 31;
    int br = tid >> 5;

    for (int i = tid; i < H * HS; i += NTHR) h_s[i] = 0.0f;

    float cst[4][4];
    #pragma unroll
    for (int b = 0; b < 4; b++)
        #pragma unroll
        for (int d = 0; d < 4; d++) cst[b][d] = 0.0f;

    float4 bo = *(const float4*)(b_out + ob * 4);
    ull bo01 = pack2(bo.x, bo.y);
    ull bo23 = pack2(bo.z, bo.w);

    const float* xgp = g_xg + (size_t)row0 * G4;
    __syncthreads();

    for (int t = 0; t < TSTEPS; t++) {
        // ---- gates = x_gates + h @ W_hh^T  (packed f32x2, 32 FFMA2/thread/k) ----
        ull acc2[4][8];
        #pragma unroll
        for (int b = 0; b < 4; b++) {
            #pragma unroll
            for (int gate = 0; gate < 4; gate++) {
                ulonglong2 v = *(const ulonglong2*)(xgp + (size_t)(4*bb + b) * G4 + gate * H + jj * 4);
                acc2[b][gate*2+0] = v.x;
                acc2[b][gate*2+1] = v.y;
            }
        }

        #pragma unroll 4
        for (int k = 0; k < H; k++) {
            float4 hv = *(const float4*)(h_s + k * HS + 4 * bb);
            ull h2[4] = { pack2(hv.x, hv.x), pack2(hv.y, hv.y),
                          pack2(hv.z, hv.z), pack2(hv.w, hv.w) };
            #pragma unroll
            for (int gate = 0; gate < 4; gate++) {
                ulonglong2 wv = *(const ulonglong2*)(g_WhhT + (size_t)k * G4 + gate * H + jj * 4);
                #pragma unroll
                for (int b = 0; b < 4; b++) {
                    fma2(acc2[b][gate*2+0], h2[b], wv.x);
                    fma2(acc2[b][gate*2+1], h2[b], wv.y);
                }
            }
        }
        __syncthreads();   // all reads of old h_s done before writes

        // ---- cell update (register-local: thread owns matching i,f,g,o) ----
        #pragma unroll
        for (int b = 0; b < 4; b++) {
            float g[16];
            #pragma unroll
            for (int gate = 0; gate < 4; gate++) {
                unpack2(acc2[b][gate*2+0], g[gate*4+0], g[gate*4+1]);
                unpack2(acc2[b][gate*2+1], g[gate*4+2], g[gate*4+3]);
            }
            #pragma unroll
            for (int d = 0; d < 4; d++) {
                float iv = g[0  + d];
                float fv = g[4  + d];
                float gv = g[8  + d];
                float ov = g[12 + d];
                float c = fast_sigmoid(fv) * cst[b][d] + fast_sigmoid(iv) * fast_tanh(gv);
                cst[b][d] = c;
                float h = fast_sigmoid(ov) * fast_tanh(c);
                h_s[(jj * 4 + d) * HS + 4 * bb + b] = h;   // transposed [k][b] write
            }
        }
        __syncthreads();   // h_new visible to all

        // ---- y = h_new @ W_out^T + b_out  (packed f32x2) ----
        ull ya[2][2] = { {bo01, bo23}, {bo01, bo23} };
        #pragma unroll 8
        for (int k = 0; k < H; k++) {
            float2 hp = *(const float2*)(h_s + k * HS + 2 * br);
            ull ha = pack2(hp.x, hp.x);
            ull hb = pack2(hp.y, hp.y);
            ulonglong2 wv = *(const ulonglong2*)(g_WoutT + (size_t)k * OSZ + ob * 4);
            fma2(ya[0][0], ha, wv.x);
            fma2(ya[0][1], ha, wv.y);
            fma2(ya[1][0], hb, wv.x);
            fma2(ya[1][1], hb, wv.y);
        }
        float* yp = ys + ((size_t)t * BSZ + row0) * OSZ;
        {
            ulonglong2 v0; v0.x = ya[0][0]; v0.y = ya[0][1];
            ulonglong2 v1; v1.x = ya[1][0]; v1.y = ya[1][1];
            *(ulonglong2*)(yp + (size_t)(2*br)     * OSZ + ob * 4) = v0;
            *(ulonglong2*)(yp + (size_t)(2*br + 1) * OSZ + ob * 4) = v1;
        }
        // no barrier needed: next k-loop only READS h_s; next write is after next sync
    }
}

// ---------------------------------------------------------------------------
extern "C" void kernel_launch(void* const* d_in, const int* in_sizes, int n_in,
                              void* d_out, int out_size) {
    const float* C    = (const float*)d_in[0];
    const float* Wih  = (const float*)d_in[1];
    const float* Whh  = (const float*)d_in[2];
    const float* bih  = (const float*)d_in[3];
    const float* bhh  = (const float*)d_in[4];
    const float* Wout = (const float*)d_in[5];
    const float* bout = (const float*)d_in[6];
    float* ys = (float*)d_out;

    transpose_kernel<<<(H * G4 + 255) / 256, 256>>>(Wih, Whh, Wout);
    xgates_kernel<<<NCTA, NTHR>>>(C, bih, bhh);
    lstm_kernel<<<NCTA, NTHR>>>(bout, ys);
}